// round 13
// baseline (speedup 1.0000x reference)
#include <cuda_runtime.h>
#include <math.h>

#define NB 8
#define NG 32768
#define NA 64
#define ND 128
#define GT 64
#define BSTRIDE 132
#define NT_TAB 4096
#define NTILE_SYM 136      // upper-triangular 4x4 tiles of 64x64
#define DQP 64             // points per densQK block

// ---- scratch (static device allocations are allowed) ----
__device__ float g_G[NB*64*64];            // gto^T gto per molecule
__device__ float g_Mpk[NB*NTILE_SYM*16];   // packed symmetric M (off-diag doubled)
__device__ float g_dens[NB*NG];
__device__ float g_table[NT_TAB];
__device__ unsigned g_densmax_u;
__device__ float g_u[ND];
__device__ float g_t[ND];
__device__ float g_W1t[ND*ND];
__device__ float g_W2t[ND*ND];

static __device__ __forceinline__ void fma4(float* acc, float v, float4 w) {
    acc[0] = fmaf(v, w.x, acc[0]);
    acc[1] = fmaf(v, w.y, acc[1]);
    acc[2] = fmaf(v, w.z, acc[2]);
    acc[3] = fmaf(v, w.w, acc[3]);
}

static __device__ __forceinline__ float gto_val(float d, int q, float z) {
    float zd = z * d;
    float p  = (q == 0) ? 1.0f : ((q == 1) ? d : d*d);
    return p * __expf(-zd*zd);
}

// packed upper-tri tile index for 4x4 tile (TI,TJ), TI<=TJ, 16x16 tile grid
static __device__ __forceinline__ int tsym(int TI, int TJ) {
    return TI*16 - (TI*(TI+1))/2 + TJ;
}

// ---------- setup ----------
__global__ void setupK(float* out, const float* __restrict__ wpb,
                       const float* __restrict__ wprew, const float* __restrict__ wpreb,
                       const float* __restrict__ wfw,   const float* __restrict__ wfb) {
    int bid = blockIdx.x, tid = threadIdx.x;
    if (bid == 0) {
        if (tid < NB) out[tid] = wpb[0];
        if (tid == 0) g_densmax_u = 0u;
    } else if (bid == 1) {
        if (tid < ND) {
            int e = tid;
            float u = 0.f, t = 0.f;
            for (int d = 0; d < ND; d++) {
                float w = wfw[e*ND + d];
                u = fmaf(w, wprew[d], u);
                t = fmaf(w, wpreb[d], t);
            }
            g_u[e] = u;
            g_t[e] = t + wfb[e];
        }
    } else if (bid <= 3) {
        float* dst = (bid == 2) ? g_W1t : g_W2t;
        const float* src = wfw + (bid - 1) * ND * ND;
        for (int i = tid; i < ND*ND; i += 256) {
            int e = i >> 7, d = i & 127;
            dst[d*ND + e] = src[i];
        }
    } else {
        int b = bid - 4;
        for (int i = tid; i < 64*64; i += 256) g_G[b*4096 + i] = 0.f;
    }
}

// ---------- pass 1: gto from dist, syrk G += gto^T gto (4x4 tiles, k split x2) ----------
#define G_SMEM ((128*68 + 64 + 64) * 4)
__global__ void __launch_bounds__(320) gtoGK(const float* __restrict__ dist,
                                             const int* __restrict__ qn,
                                             const int* __restrict__ ao,
                                             const float* __restrict__ zeta) {
    extern __shared__ float sm[];
    float* tile = sm;                    // [128][68]
    float* zs   = sm + 128*68;
    int*   qs   = (int*)(zs + 64);
    int tid = threadIdx.x;
    int b   = blockIdx.y;

    if (tid < 64) {
        qs[tid] = qn[b*NA + tid];
        zs[tid] = zeta[ao[b*NA + tid]];
    }

    // thread -> (kg, upper-tri 4x4 tile (ti,tj)); threads 0..271 active
    bool active = (tid < 2*NTILE_SYM);
    int kg = tid / NTILE_SYM;            // 0 or 1 -> k in [64kg, 64kg+64)
    int s  = tid % NTILE_SYM;
    int ti = 0, tj = 0;
    {
        int t = s;
        while (ti < 16 && t >= 16 - ti) { t -= 16 - ti; ti++; }
        tj = ti + t;
    }

    float C[4][4];
    #pragma unroll
    for (int r = 0; r < 4; r++)
        #pragma unroll
        for (int c = 0; c < 4; c++) C[r][c] = 0.f;

    __syncthreads();

    for (int tl = blockIdx.x; tl < NG/128; tl += gridDim.x) {
        long base = ((long)b*NG + (long)tl*128) * NA;
        for (int i = tid; i < 128*16; i += 320) {
            int p = i >> 4, c = i & 15;
            float4 dv = *(const float4*)(dist + base + (long)p*NA + 4*c);
            float4 gv;
            gv.x = gto_val(dv.x, qs[4*c+0], zs[4*c+0]);
            gv.y = gto_val(dv.y, qs[4*c+1], zs[4*c+1]);
            gv.z = gto_val(dv.z, qs[4*c+2], zs[4*c+2]);
            gv.w = gto_val(dv.w, qs[4*c+3], zs[4*c+3]);
            *(float4*)&tile[p*68 + 4*c] = gv;
        }
        __syncthreads();
        if (active) {
            int k0 = kg * 64;
            #pragma unroll 4
            for (int k = k0; k < k0 + 64; k++) {
                float4 ai = *(const float4*)&tile[k*68 + 4*ti];
                float4 aj = *(const float4*)&tile[k*68 + 4*tj];
                fma4(C[0], ai.x, aj); fma4(C[1], ai.y, aj);
                fma4(C[2], ai.z, aj); fma4(C[3], ai.w, aj);
            }
        }
        __syncthreads();
    }

    if (active) {
        float* Gb = g_G + b*4096;
        if (ti == tj) {
            #pragma unroll
            for (int r = 0; r < 4; r++)
                #pragma unroll
                for (int c = 0; c < 4; c++)
                    atomicAdd(&Gb[(4*ti + r)*64 + 4*tj + c], C[r][c]);
        } else {
            #pragma unroll
            for (int r = 0; r < 4; r++)
                #pragma unroll
                for (int c = 0; c < 4; c++) {
                    atomicAdd(&Gb[(4*ti + r)*64 + 4*tj + c], C[r][c]);
                    atomicAdd(&Gb[(4*tj + c)*64 + 4*ti + r], C[r][c]);
                }
        }
    }
}

// ---------- fused prep: ceff -> monorm -> packed M ----------
#define PF_SMEM ((4096 + 8448 + 64 + 128 + 128 + 256) * 4 + 64*4)
__global__ void __launch_bounds__(256) prepFK(const int* __restrict__ ao,
                                              const float* __restrict__ coef,
                                              const float* __restrict__ Ne) {
    extern __shared__ float sm[];
    float* Gs    = sm;                    // 4096
    float* ceffS = Gs + 4096;             // 64*132
    float* rg    = ceffS + 8448;          // 64
    float* rc    = rg + 64;               // 128
    float* inv   = rc + 128;              // 128
    float* mpart = inv + 128;             // 256
    int*   aos   = (int*)(mpart + 256);   // 64
    int b = blockIdx.x, tid = threadIdx.x;

    for (int i = tid; i < 4096; i += 256) Gs[i] = g_G[b*4096 + i];
    if (tid < 64) aos[tid] = ao[b*NA + tid];
    __syncthreads();
    if (tid < 64) rg[tid] = 1.f / fmaxf(sqrtf(Gs[tid*64 + tid]), 1e-12f);

    for (int i = tid; i < 64*128; i += 256) {
        int a = i >> 7, d = i & 127;
        ceffS[a*132 + d] = coef[aos[a]*ND + d];
    }
    __syncthreads();

    if (tid < 128) {
        float cn = 0.f;
        #pragma unroll 8
        for (int a = 0; a < 64; a++) { float c = ceffS[a*132 + tid]; cn = fmaf(c, c, cn); }
        rc[tid] = 1.f / fmaxf(sqrtf(cn), 1e-12f);
    }
    __syncthreads();
    for (int i = tid; i < 64*128; i += 256) {
        int a = i >> 7, d = i & 127;
        ceffS[a*132 + d] *= rc[d] * rg[a];
    }
    __syncthreads();

    {
        int d = tid & 127, h = tid >> 7;
        float c[64];
        #pragma unroll
        for (int a = 0; a < 64; a++) c[a] = ceffS[a*132 + d];
        float m = 0.f;
        int i0 = 32*h;
        for (int i = i0; i < i0 + 32; i++) {
            const float4* row = (const float4*)&Gs[i*64];
            float y0 = 0.f, y1 = 0.f, y2 = 0.f, y3 = 0.f;
            #pragma unroll
            for (int k = 0; k < 4; k++) {
                float4 ga = row[k],     gb = row[k+4];
                float4 gc = row[k+8],   gd = row[k+12];
                y0 = fmaf(ga.x, c[4*k+0],  y0); y0 = fmaf(ga.y, c[4*k+1],  y0);
                y0 = fmaf(ga.z, c[4*k+2],  y0); y0 = fmaf(ga.w, c[4*k+3],  y0);
                y1 = fmaf(gb.x, c[16+4*k+0], y1); y1 = fmaf(gb.y, c[16+4*k+1], y1);
                y1 = fmaf(gb.z, c[16+4*k+2], y1); y1 = fmaf(gb.w, c[16+4*k+3], y1);
                y2 = fmaf(gc.x, c[32+4*k+0], y2); y2 = fmaf(gc.y, c[32+4*k+1], y2);
                y2 = fmaf(gc.z, c[32+4*k+2], y2); y2 = fmaf(gc.w, c[32+4*k+3], y2);
                y3 = fmaf(gd.x, c[48+4*k+0], y3); y3 = fmaf(gd.y, c[48+4*k+1], y3);
                y3 = fmaf(gd.z, c[48+4*k+2], y3); y3 = fmaf(gd.w, c[48+4*k+3], y3);
            }
            m = fmaf(y0 + y1 + y2 + y3, c[i], m);
        }
        mpart[h*128 + d] = m;
    }
    __syncthreads();
    if (tid < 128) {
        float m = mpart[tid] + mpart[128 + tid];
        float s2 = Ne[b] / (float)ND;
        inv[tid] = sqrtf(s2 / fmaxf(m, 1e-24f));
    }
    __syncthreads();
    for (int i = tid; i < 64*128; i += 256) {
        int a = i >> 7, d = i & 127;
        ceffS[a*132 + d] *= inv[d];
    }
    __syncthreads();

    if (tid < NTILE_SYM) {
        int ti = 0, tj = 0;
        {
            int t = tid;
            while (ti < 16 && t >= 16 - ti) { t -= 16 - ti; ti++; }
            tj = ti + t;
        }
        float acc[4][4];
        #pragma unroll
        for (int r = 0; r < 4; r++)
            #pragma unroll
            for (int c = 0; c < 4; c++) acc[r][c] = 0.f;
        for (int d = 0; d < 128; d++) {
            float ci[4], cj[4];
            #pragma unroll
            for (int r = 0; r < 4; r++) ci[r] = ceffS[(4*ti + r)*132 + d];
            #pragma unroll
            for (int c = 0; c < 4; c++) cj[c] = ceffS[(4*tj + c)*132 + d];
            #pragma unroll
            for (int r = 0; r < 4; r++)
                #pragma unroll
                for (int c = 0; c < 4; c++) acc[r][c] = fmaf(ci[r], cj[c], acc[r][c]);
        }
        float sc = (ti == tj) ? 1.0f : 2.0f;
        float* dst = g_Mpk + b*NTILE_SYM*16 + tid*16;
        #pragma unroll
        for (int r = 0; r < 4; r++)
            #pragma unroll
            for (int c = 0; c < 4; c++) dst[r*4 + c] = acc[r][c] * sc;
    }
}

// ---------- pass 2: dens = g^T M g, thread-pair per point (R9, proven) ----------
#define DQ_SMEM ((DQP*68 + NTILE_SYM*16 + 64 + DQP) * 4 + 64*4)
__global__ void __launch_bounds__(128, 8) densQK(const float* __restrict__ dist,
                                                 const int* __restrict__ qn,
                                                 const int* __restrict__ ao,
                                                 const float* __restrict__ zeta) {
    extern __shared__ float sm[];
    float* gt = sm;                        // [DQP][68]
    float* Mp = gt + DQP*68;               // 2176
    float* zs = Mp + NTILE_SYM*16;         // 64
    float* pd = zs + 64;                   // DQP partials
    int*   qs = (int*)(pd + DQP);          // 64
    int tid = threadIdx.x;
    int b   = blockIdx.y;
    int g0  = blockIdx.x * DQP;
    int p   = tid & 63;
    int h   = tid >> 6;                    // warp-uniform half id

    if (tid < 64) {
        qs[tid] = qn[b*NA + tid];
        zs[tid] = zeta[ao[b*NA + tid]];
    }
    for (int i = tid; i < NTILE_SYM*16; i += 128) Mp[i] = g_Mpk[b*NTILE_SYM*16 + i];
    __syncthreads();

    long base = ((long)b*NG + g0) * NA;
    for (int i = tid; i < DQP*16; i += 128) {
        int pp = i >> 4, c = i & 15;
        float4 dv = *(const float4*)(dist + base + (long)pp*NA + 4*c);
        float4 gv;
        gv.x = gto_val(dv.x, qs[4*c+0], zs[4*c+0]);
        gv.y = gto_val(dv.y, qs[4*c+1], zs[4*c+1]);
        gv.z = gto_val(dv.z, qs[4*c+2], zs[4*c+2]);
        gv.w = gto_val(dv.w, qs[4*c+3], zs[4*c+3]);
        *(float4*)&gt[pp*68 + 4*c] = gv;
    }
    __syncthreads();

    // own half into registers
    float g[32];
    {
        const float* gp = gt + p*68 + 32*h;
        #pragma unroll
        for (int k = 0; k < 8; k++) {
            float4 v = *(const float4*)(gp + 4*k);
            g[4*k+0] = v.x; g[4*k+1] = v.y; g[4*k+2] = v.z; g[4*k+3] = v.w;
        }
    }

    const float4* Mt = (const float4*)Mp;
    float dens = 0.f;

    // own-half symmetric QF: global tiles (8h+a, 8h+bb), a<=bb
    #pragma unroll
    for (int a = 0; a < 8; a++) {
        float y0 = 0.f, y1 = 0.f, y2 = 0.f, y3 = 0.f;
        #pragma unroll
        for (int bb = a; bb < 8; bb++) {
            int t = tsym(8*h + a, 8*h + bb);
            float4 m0 = Mt[4*t+0], m1 = Mt[4*t+1], m2 = Mt[4*t+2], m3 = Mt[4*t+3];
            float gj0 = g[4*bb+0], gj1 = g[4*bb+1], gj2 = g[4*bb+2], gj3 = g[4*bb+3];
            y0 = fmaf(m0.x, gj0, y0); y0 = fmaf(m0.y, gj1, y0);
            y0 = fmaf(m0.z, gj2, y0); y0 = fmaf(m0.w, gj3, y0);
            y1 = fmaf(m1.x, gj0, y1); y1 = fmaf(m1.y, gj1, y1);
            y1 = fmaf(m1.z, gj2, y1); y1 = fmaf(m1.w, gj3, y1);
            y2 = fmaf(m2.x, gj0, y2); y2 = fmaf(m2.y, gj1, y2);
            y2 = fmaf(m2.z, gj2, y2); y2 = fmaf(m2.w, gj3, y2);
            y3 = fmaf(m3.x, gj0, y3); y3 = fmaf(m3.y, gj1, y3);
            y3 = fmaf(m3.z, gj2, y3); y3 = fmaf(m3.w, gj3, y3);
        }
        float s = g[4*a+0]*y0 + g[4*a+1]*y1;
        s = fmaf(g[4*a+2], y2, s);
        s = fmaf(g[4*a+3], y3, s);
        dens += s;
    }

    // cross block: tiles (a, 8+bb), split by bb range
    if (h == 0) {
        #pragma unroll
        for (int bb = 0; bb < 4; bb++) {
            float4 gj = *(const float4*)&gt[p*68 + 32 + 4*bb];
            float w0 = 0.f, w1 = 0.f, w2 = 0.f, w3 = 0.f;
            #pragma unroll
            for (int a = 0; a < 8; a++) {
                int t = tsym(a, 8 + bb);
                float4 m0 = Mt[4*t+0], m1 = Mt[4*t+1], m2 = Mt[4*t+2], m3 = Mt[4*t+3];
                float gi0 = g[4*a+0], gi1 = g[4*a+1], gi2 = g[4*a+2], gi3 = g[4*a+3];
                w0 = fmaf(m0.x, gi0, w0); w1 = fmaf(m0.y, gi0, w1);
                w2 = fmaf(m0.z, gi0, w2); w3 = fmaf(m0.w, gi0, w3);
                w0 = fmaf(m1.x, gi1, w0); w1 = fmaf(m1.y, gi1, w1);
                w2 = fmaf(m1.z, gi1, w2); w3 = fmaf(m1.w, gi1, w3);
                w0 = fmaf(m2.x, gi2, w0); w1 = fmaf(m2.y, gi2, w1);
                w2 = fmaf(m2.z, gi2, w2); w3 = fmaf(m2.w, gi2, w3);
                w0 = fmaf(m3.x, gi3, w0); w1 = fmaf(m3.y, gi3, w1);
                w2 = fmaf(m3.z, gi3, w2); w3 = fmaf(m3.w, gi3, w3);
            }
            float s = w0*gj.x + w1*gj.y;
            s = fmaf(w2, gj.z, s);
            s = fmaf(w3, gj.w, s);
            dens += s;
        }
    } else {
        #pragma unroll
        for (int a = 0; a < 8; a++) {
            float v0 = 0.f, v1 = 0.f, v2 = 0.f, v3 = 0.f;
            #pragma unroll
            for (int bb = 4; bb < 8; bb++) {
                int t = tsym(a, 8 + bb);
                float4 m0 = Mt[4*t+0], m1 = Mt[4*t+1], m2 = Mt[4*t+2], m3 = Mt[4*t+3];
                float gj0 = g[4*bb+0], gj1 = g[4*bb+1], gj2 = g[4*bb+2], gj3 = g[4*bb+3];
                v0 = fmaf(m0.x, gj0, v0); v0 = fmaf(m0.y, gj1, v0);
                v0 = fmaf(m0.z, gj2, v0); v0 = fmaf(m0.w, gj3, v0);
                v1 = fmaf(m1.x, gj0, v1); v1 = fmaf(m1.y, gj1, v1);
                v1 = fmaf(m1.z, gj2, v1); v1 = fmaf(m1.w, gj3, v1);
                v2 = fmaf(m2.x, gj0, v2); v2 = fmaf(m2.y, gj1, v2);
                v2 = fmaf(m2.z, gj2, v2); v2 = fmaf(m2.w, gj3, v2);
                v3 = fmaf(m3.x, gj0, v3); v3 = fmaf(m3.y, gj1, v3);
                v3 = fmaf(m3.z, gj2, v3); v3 = fmaf(m3.w, gj3, v3);
            }
            float4 gi = *(const float4*)&gt[p*68 + 4*a];
            float s = gi.x*v0 + gi.y*v1;
            s = fmaf(gi.z, v2, s);
            s = fmaf(gi.w, v3, s);
            dens += s;
        }
    }

    if (h == 1) pd[p] = dens;
    __syncthreads();
    if (h == 0) {
        float d = dens + pd[p];
        g_dens[(long)b*NG + g0 + p] = d;
        float mx = d;
        #pragma unroll
        for (int off = 16; off; off >>= 1)
            mx = fmaxf(mx, __shfl_xor_sync(0xffffffffu, mx, off));
        if ((tid & 31) == 0) atomicMax(&g_densmax_u, __float_as_uint(mx));
    }
}

// ---------- table: phi at NT_TAB nodes over [0, densmax] ----------
__global__ void __launch_bounds__(256) tableK(const float* __restrict__ wfb,
                                              const float* __restrict__ wpw) {
    extern __shared__ float sm[];
    float* W1   = sm;
    float* W2   = W1 + ND*ND;
    float* bufA = W2 + ND*ND;
    float* bufB = bufA + GT*ND;
    float* us   = bufB + GT*BSTRIDE;
    float* ts   = us  + ND;
    float* b1s  = ts  + ND;
    float* b2s  = b1s + ND;
    float* wps  = b2s + ND;
    int tid = threadIdx.x;

    for (int i = tid; i < ND*ND; i += 256) { W1[i] = g_W1t[i]; W2[i] = g_W2t[i]; }
    if (tid < ND) {
        us[tid]  = g_u[tid];
        ts[tid]  = g_t[tid];
        b1s[tid] = wfb[ND + tid];
        b2s[tid] = wfb[2*ND + tid];
        wps[tid] = wpw[tid];
    }
    float h = __uint_as_float(g_densmax_u) / (float)(NT_TAB - 1);
    __syncthreads();

    int t0 = blockIdx.x * GT;
    for (int i = tid; i < GT*ND; i += 256) {
        int g = i >> 7, e = i & 127;
        float x = (float)(t0 + g) * h;
        bufA[i] = fmaxf(fmaf(x, us[e], ts[e]), 0.f);
    }
    __syncthreads();

    int eq = tid & 31, gq = tid >> 5;
    float acc[8][4];
    {
        float4 bb = *(const float4*)&b1s[4*eq];
        #pragma unroll
        for (int r = 0; r < 8; r++) { acc[r][0]=bb.x; acc[r][1]=bb.y; acc[r][2]=bb.z; acc[r][3]=bb.w; }
    }
    #pragma unroll 4
    for (int d4 = 0; d4 < 32; d4++) {
        float4 w[4];
        #pragma unroll
        for (int k = 0; k < 4; k++) w[k] = *(const float4*)&W1[(4*d4 + k)*ND + 4*eq];
        #pragma unroll
        for (int r = 0; r < 8; r++) {
            float4 v = *(const float4*)&bufA[(gq*8 + r)*ND + 4*d4];
            fma4(acc[r], v.x, w[0]); fma4(acc[r], v.y, w[1]);
            fma4(acc[r], v.z, w[2]); fma4(acc[r], v.w, w[3]);
        }
    }
    #pragma unroll
    for (int r = 0; r < 8; r++) {
        float4 o = make_float4(fmaxf(acc[r][0],0.f), fmaxf(acc[r][1],0.f),
                               fmaxf(acc[r][2],0.f), fmaxf(acc[r][3],0.f));
        *(float4*)&bufB[(gq*8 + r)*BSTRIDE + 4*eq] = o;
    }
    __syncthreads();

    {
        float4 bb = *(const float4*)&b2s[4*eq];
        #pragma unroll
        for (int r = 0; r < 8; r++) { acc[r][0]=bb.x; acc[r][1]=bb.y; acc[r][2]=bb.z; acc[r][3]=bb.w; }
    }
    #pragma unroll 4
    for (int d4 = 0; d4 < 32; d4++) {
        float4 w[4];
        #pragma unroll
        for (int k = 0; k < 4; k++) w[k] = *(const float4*)&W2[(4*d4 + k)*ND + 4*eq];
        #pragma unroll
        for (int r = 0; r < 8; r++) {
            float4 v = *(const float4*)&bufB[(gq*8 + r)*BSTRIDE + 4*d4];
            fma4(acc[r], v.x, w[0]); fma4(acc[r], v.y, w[1]);
            fma4(acc[r], v.z, w[2]); fma4(acc[r], v.w, w[3]);
        }
    }
    float4 wp4 = *(const float4*)&wps[4*eq];
    #pragma unroll
    for (int r = 0; r < 8; r++) {
        float v = fmaxf(acc[r][0],0.f)*wp4.x + fmaxf(acc[r][1],0.f)*wp4.y
                + fmaxf(acc[r][2],0.f)*wp4.z + fmaxf(acc[r][3],0.f)*wp4.w;
        #pragma unroll
        for (int off = 16; off; off >>= 1) v += __shfl_xor_sync(0xffffffffu, v, off);
        if (eq == 0) g_table[t0 + gq*8 + r] = v;
    }
}

// ---------- final: E[b] += sum_g lerp(table, dens) ----------
__global__ void __launch_bounds__(256) sumK(float* __restrict__ out) {
    extern __shared__ float T[];
    float* red = T + NT_TAB;
    int tid = threadIdx.x;
    for (int i = tid; i < NT_TAB/4; i += 256)
        ((float4*)T)[i] = ((const float4*)g_table)[i];
    __syncthreads();
    float invh = (float)(NT_TAB - 1) / __uint_as_float(g_densmax_u);
    int b = blockIdx.y;
    const int chunk = NG / 8;
    long base = (long)b*NG + blockIdx.x*chunk;
    float acc = 0.f;
    for (int i = tid; i < chunk; i += 256) {
        float dn = g_dens[base + i];
        float t  = dn * invh;
        int ix = min((int)t, NT_TAB - 2);
        float f = t - (float)ix;
        acc += fmaf(f, T[ix+1] - T[ix], T[ix]);
    }
    #pragma unroll
    for (int off = 16; off; off >>= 1) acc += __shfl_xor_sync(0xffffffffu, acc, off);
    if ((tid & 31) == 0) red[tid >> 5] = acc;
    __syncthreads();
    if (tid == 0) {
        float s = 0.f;
        #pragma unroll
        for (int w = 0; w < 8; w++) s += red[w];
        atomicAdd(&out[b], s);
    }
}

extern "C" void kernel_launch(void* const* d_in, const int* in_sizes, int n_in,
                              void* d_out, int out_size) {
    const float* dist  = (const float*)d_in[0];
    const int*   qn    = (const int*)  d_in[1];
    const int*   ao    = (const int*)  d_in[2];
    const float* Ne    = (const float*)d_in[3];
    const float* coef  = (const float*)d_in[4];
    const float* zeta  = (const float*)d_in[5];
    const float* wprew = (const float*)d_in[6];
    const float* wpreb = (const float*)d_in[7];
    const float* wfw   = (const float*)d_in[8];
    const float* wfb   = (const float*)d_in[9];
    const float* wpw   = (const float*)d_in[10];
    const float* wpb   = (const float*)d_in[11];
    float* out = (float*)d_out;

    const int tabSmem = (ND*ND*2 + GT*ND + GT*BSTRIDE + ND*5) * 4;
    const int sumSmem = (NT_TAB + 8) * 4;
    cudaFuncSetAttribute(gtoGK,  cudaFuncAttributeMaxDynamicSharedMemorySize, G_SMEM);
    cudaFuncSetAttribute(prepFK, cudaFuncAttributeMaxDynamicSharedMemorySize, PF_SMEM);
    cudaFuncSetAttribute(densQK, cudaFuncAttributeMaxDynamicSharedMemorySize, DQ_SMEM);
    cudaFuncSetAttribute(tableK, cudaFuncAttributeMaxDynamicSharedMemorySize, tabSmem);
    cudaFuncSetAttribute(sumK,   cudaFuncAttributeMaxDynamicSharedMemorySize, sumSmem);

    setupK<<<12, 256>>>(out, wpb, wprew, wpreb, wfw, wfb);
    gtoGK<<<dim3(111, NB), 320, G_SMEM>>>(dist, qn, ao, zeta);
    prepFK<<<NB, 256, PF_SMEM>>>(ao, coef, Ne);
    densQK<<<dim3(NG/DQP, NB), 128, DQ_SMEM>>>(dist, qn, ao, zeta);
    tableK<<<NT_TAB/GT, 256, tabSmem>>>(wfb, wpw);
    sumK<<<dim3(8, NB), 256, sumSmem>>>(out);
}

// round 14
// speedup vs baseline: 1.0082x; 1.0082x over previous
#include <cuda_runtime.h>
#include <math.h>

#define NB 8
#define NG 32768
#define NA 64
#define ND 128
#define GT 64
#define BSTRIDE 132
#define NT_TAB 4096
#define NTILE_SYM 136      // upper-triangular 4x4 tiles of 64x64
#define DQP 64             // points per densQK block

// ---- scratch (static device allocations are allowed) ----
__device__ float g_G[NB*64*64];            // gto^T gto per molecule
__device__ float g_Mpk[NB*NTILE_SYM*16];   // packed symmetric M (off-diag doubled)
__device__ float g_dens[NB*NG];
__device__ float g_table[NT_TAB];
__device__ unsigned g_densmax_u;
__device__ float g_u[ND];
__device__ float g_t[ND];
__device__ float g_W1t[ND*ND];
__device__ float g_W2t[ND*ND];

static __device__ __forceinline__ void fma4(float* acc, float v, float4 w) {
    acc[0] = fmaf(v, w.x, acc[0]);
    acc[1] = fmaf(v, w.y, acc[1]);
    acc[2] = fmaf(v, w.z, acc[2]);
    acc[3] = fmaf(v, w.w, acc[3]);
}

static __device__ __forceinline__ float gto_val(float d, int q, float z) {
    float zd = z * d;
    float p  = (q == 0) ? 1.0f : ((q == 1) ? d : d*d);
    return p * __expf(-zd*zd);
}

// packed upper-tri tile index for 4x4 tile (TI,TJ), TI<=TJ, 16x16 tile grid
static __device__ __forceinline__ int tsym(int TI, int TJ) {
    return TI*16 - (TI*(TI+1))/2 + TJ;
}

// ---------- setup ----------
__global__ void setupK(float* out, const float* __restrict__ wpb,
                       const float* __restrict__ wprew, const float* __restrict__ wpreb,
                       const float* __restrict__ wfw,   const float* __restrict__ wfb) {
    int bid = blockIdx.x, tid = threadIdx.x;
    if (bid == 0) {
        if (tid < NB) out[tid] = wpb[0];
        if (tid == 0) g_densmax_u = 0u;
    } else if (bid == 1) {
        if (tid < ND) {
            int e = tid;
            float u = 0.f, t = 0.f;
            for (int d = 0; d < ND; d++) {
                float w = wfw[e*ND + d];
                u = fmaf(w, wprew[d], u);
                t = fmaf(w, wpreb[d], t);
            }
            g_u[e] = u;
            g_t[e] = t + wfb[e];
        }
    } else if (bid <= 3) {
        float* dst = (bid == 2) ? g_W1t : g_W2t;
        const float* src = wfw + (bid - 1) * ND * ND;
        for (int i = tid; i < ND*ND; i += 256) {
            int e = i >> 7, d = i & 127;
            dst[d*ND + e] = src[i];
        }
    } else {
        int b = bid - 4;
        for (int i = tid; i < 64*64; i += 256) g_G[b*4096 + i] = 0.f;
    }
}

// ---------- pass 1: gto from dist, syrk G += gto^T gto (4x4 tiles, k split x2) ----------
#define G_SMEM ((128*68 + 64 + 64) * 4)
__global__ void __launch_bounds__(320) gtoGK(const float* __restrict__ dist,
                                             const int* __restrict__ qn,
                                             const int* __restrict__ ao,
                                             const float* __restrict__ zeta) {
    extern __shared__ float sm[];
    float* tile = sm;                    // [128][68]
    float* zs   = sm + 128*68;
    int*   qs   = (int*)(zs + 64);
    int tid = threadIdx.x;
    int b   = blockIdx.y;

    if (tid < 64) {
        qs[tid] = qn[b*NA + tid];
        zs[tid] = zeta[ao[b*NA + tid]];
    }

    // thread -> (kg, upper-tri 4x4 tile (ti,tj)); threads 0..271 active
    bool active = (tid < 2*NTILE_SYM);
    int kg = tid / NTILE_SYM;            // 0 or 1 -> k in [64kg, 64kg+64)
    int s  = tid % NTILE_SYM;
    int ti = 0, tj = 0;
    {
        int t = s;
        while (ti < 16 && t >= 16 - ti) { t -= 16 - ti; ti++; }
        tj = ti + t;
    }

    float C[4][4];
    #pragma unroll
    for (int r = 0; r < 4; r++)
        #pragma unroll
        for (int c = 0; c < 4; c++) C[r][c] = 0.f;

    __syncthreads();

    for (int tl = blockIdx.x; tl < NG/128; tl += gridDim.x) {
        long base = ((long)b*NG + (long)tl*128) * NA;
        for (int i = tid; i < 128*16; i += 320) {
            int p = i >> 4, c = i & 15;
            float4 dv = *(const float4*)(dist + base + (long)p*NA + 4*c);
            float4 gv;
            gv.x = gto_val(dv.x, qs[4*c+0], zs[4*c+0]);
            gv.y = gto_val(dv.y, qs[4*c+1], zs[4*c+1]);
            gv.z = gto_val(dv.z, qs[4*c+2], zs[4*c+2]);
            gv.w = gto_val(dv.w, qs[4*c+3], zs[4*c+3]);
            *(float4*)&tile[p*68 + 4*c] = gv;
        }
        __syncthreads();
        if (active) {
            int k0 = kg * 64;
            #pragma unroll 4
            for (int k = k0; k < k0 + 64; k++) {
                float4 ai = *(const float4*)&tile[k*68 + 4*ti];
                float4 aj = *(const float4*)&tile[k*68 + 4*tj];
                fma4(C[0], ai.x, aj); fma4(C[1], ai.y, aj);
                fma4(C[2], ai.z, aj); fma4(C[3], ai.w, aj);
            }
        }
        __syncthreads();
    }

    if (active) {
        float* Gb = g_G + b*4096;
        if (ti == tj) {
            #pragma unroll
            for (int r = 0; r < 4; r++)
                #pragma unroll
                for (int c = 0; c < 4; c++)
                    atomicAdd(&Gb[(4*ti + r)*64 + 4*tj + c], C[r][c]);
        } else {
            #pragma unroll
            for (int r = 0; r < 4; r++)
                #pragma unroll
                for (int c = 0; c < 4; c++) {
                    atomicAdd(&Gb[(4*ti + r)*64 + 4*tj + c], C[r][c]);
                    atomicAdd(&Gb[(4*tj + c)*64 + 4*ti + r], C[r][c]);
                }
        }
    }
}

// ---------- fused prep: ceff -> monorm -> packed M ----------
#define PF_SMEM ((4096 + 8448 + 64 + 128 + 128 + 256) * 4 + 64*4)
__global__ void __launch_bounds__(256) prepFK(const int* __restrict__ ao,
                                              const float* __restrict__ coef,
                                              const float* __restrict__ Ne) {
    extern __shared__ float sm[];
    float* Gs    = sm;                    // 4096
    float* ceffS = Gs + 4096;             // 64*132
    float* rg    = ceffS + 8448;          // 64
    float* rc    = rg + 64;               // 128
    float* inv   = rc + 128;              // 128
    float* mpart = inv + 128;             // 256
    int*   aos   = (int*)(mpart + 256);   // 64
    int b = blockIdx.x, tid = threadIdx.x;

    for (int i = tid; i < 4096; i += 256) Gs[i] = g_G[b*4096 + i];
    if (tid < 64) aos[tid] = ao[b*NA + tid];
    __syncthreads();
    if (tid < 64) rg[tid] = 1.f / fmaxf(sqrtf(Gs[tid*64 + tid]), 1e-12f);

    for (int i = tid; i < 64*128; i += 256) {
        int a = i >> 7, d = i & 127;
        ceffS[a*132 + d] = coef[aos[a]*ND + d];
    }
    __syncthreads();

    if (tid < 128) {
        float cn = 0.f;
        #pragma unroll 8
        for (int a = 0; a < 64; a++) { float c = ceffS[a*132 + tid]; cn = fmaf(c, c, cn); }
        rc[tid] = 1.f / fmaxf(sqrtf(cn), 1e-12f);
    }
    __syncthreads();
    for (int i = tid; i < 64*128; i += 256) {
        int a = i >> 7, d = i & 127;
        ceffS[a*132 + d] *= rc[d] * rg[a];
    }
    __syncthreads();

    {
        int d = tid & 127, h = tid >> 7;
        float c[64];
        #pragma unroll
        for (int a = 0; a < 64; a++) c[a] = ceffS[a*132 + d];
        float m = 0.f;
        int i0 = 32*h;
        for (int i = i0; i < i0 + 32; i++) {
            const float4* row = (const float4*)&Gs[i*64];
            float y0 = 0.f, y1 = 0.f, y2 = 0.f, y3 = 0.f;
            #pragma unroll
            for (int k = 0; k < 4; k++) {
                float4 ga = row[k],     gb = row[k+4];
                float4 gc = row[k+8],   gd = row[k+12];
                y0 = fmaf(ga.x, c[4*k+0],  y0); y0 = fmaf(ga.y, c[4*k+1],  y0);
                y0 = fmaf(ga.z, c[4*k+2],  y0); y0 = fmaf(ga.w, c[4*k+3],  y0);
                y1 = fmaf(gb.x, c[16+4*k+0], y1); y1 = fmaf(gb.y, c[16+4*k+1], y1);
                y1 = fmaf(gb.z, c[16+4*k+2], y1); y1 = fmaf(gb.w, c[16+4*k+3], y1);
                y2 = fmaf(gc.x, c[32+4*k+0], y2); y2 = fmaf(gc.y, c[32+4*k+1], y2);
                y2 = fmaf(gc.z, c[32+4*k+2], y2); y2 = fmaf(gc.w, c[32+4*k+3], y2);
                y3 = fmaf(gd.x, c[48+4*k+0], y3); y3 = fmaf(gd.y, c[48+4*k+1], y3);
                y3 = fmaf(gd.z, c[48+4*k+2], y3); y3 = fmaf(gd.w, c[48+4*k+3], y3);
            }
            m = fmaf(y0 + y1 + y2 + y3, c[i], m);
        }
        mpart[h*128 + d] = m;
    }
    __syncthreads();
    if (tid < 128) {
        float m = mpart[tid] + mpart[128 + tid];
        float s2 = Ne[b] / (float)ND;
        inv[tid] = sqrtf(s2 / fmaxf(m, 1e-24f));
    }
    __syncthreads();
    for (int i = tid; i < 64*128; i += 256) {
        int a = i >> 7, d = i & 127;
        ceffS[a*132 + d] *= inv[d];
    }
    __syncthreads();

    if (tid < NTILE_SYM) {
        int ti = 0, tj = 0;
        {
            int t = tid;
            while (ti < 16 && t >= 16 - ti) { t -= 16 - ti; ti++; }
            tj = ti + t;
        }
        float acc[4][4];
        #pragma unroll
        for (int r = 0; r < 4; r++)
            #pragma unroll
            for (int c = 0; c < 4; c++) acc[r][c] = 0.f;
        for (int d = 0; d < 128; d++) {
            float ci[4], cj[4];
            #pragma unroll
            for (int r = 0; r < 4; r++) ci[r] = ceffS[(4*ti + r)*132 + d];
            #pragma unroll
            for (int c = 0; c < 4; c++) cj[c] = ceffS[(4*tj + c)*132 + d];
            #pragma unroll
            for (int r = 0; r < 4; r++)
                #pragma unroll
                for (int c = 0; c < 4; c++) acc[r][c] = fmaf(ci[r], cj[c], acc[r][c]);
        }
        float sc = (ti == tj) ? 1.0f : 2.0f;
        float* dst = g_Mpk + b*NTILE_SYM*16 + tid*16;
        #pragma unroll
        for (int r = 0; r < 4; r++)
            #pragma unroll
            for (int c = 0; c < 4; c++) dst[r*4 + c] = acc[r][c] * sc;
    }
}

// ---------- pass 2: dens = g^T M g, thread-pair per point (R9, proven) ----------
#define DQ_SMEM ((DQP*68 + NTILE_SYM*16 + 64 + DQP) * 4 + 64*4)
__global__ void __launch_bounds__(128, 8) densQK(const float* __restrict__ dist,
                                                 const int* __restrict__ qn,
                                                 const int* __restrict__ ao,
                                                 const float* __restrict__ zeta) {
    extern __shared__ float sm[];
    float* gt = sm;                        // [DQP][68]
    float* Mp = gt + DQP*68;               // 2176
    float* zs = Mp + NTILE_SYM*16;         // 64
    float* pd = zs + 64;                   // DQP partials
    int*   qs = (int*)(pd + DQP);          // 64
    int tid = threadIdx.x;
    int b   = blockIdx.y;
    int g0  = blockIdx.x * DQP;
    int p   = tid & 63;
    int h   = tid >> 6;                    // warp-uniform half id

    if (tid < 64) {
        qs[tid] = qn[b*NA + tid];
        zs[tid] = zeta[ao[b*NA + tid]];
    }
    for (int i = tid; i < NTILE_SYM*16; i += 128) Mp[i] = g_Mpk[b*NTILE_SYM*16 + i];
    __syncthreads();

    long base = ((long)b*NG + g0) * NA;
    for (int i = tid; i < DQP*16; i += 128) {
        int pp = i >> 4, c = i & 15;
        float4 dv = *(const float4*)(dist + base + (long)pp*NA + 4*c);
        float4 gv;
        gv.x = gto_val(dv.x, qs[4*c+0], zs[4*c+0]);
        gv.y = gto_val(dv.y, qs[4*c+1], zs[4*c+1]);
        gv.z = gto_val(dv.z, qs[4*c+2], zs[4*c+2]);
        gv.w = gto_val(dv.w, qs[4*c+3], zs[4*c+3]);
        *(float4*)&gt[pp*68 + 4*c] = gv;
    }
    __syncthreads();

    // own half into registers
    float g[32];
    {
        const float* gp = gt + p*68 + 32*h;
        #pragma unroll
        for (int k = 0; k < 8; k++) {
            float4 v = *(const float4*)(gp + 4*k);
            g[4*k+0] = v.x; g[4*k+1] = v.y; g[4*k+2] = v.z; g[4*k+3] = v.w;
        }
    }

    const float4* Mt = (const float4*)Mp;
    float dens = 0.f;

    // own-half symmetric QF: global tiles (8h+a, 8h+bb), a<=bb
    #pragma unroll
    for (int a = 0; a < 8; a++) {
        float y0 = 0.f, y1 = 0.f, y2 = 0.f, y3 = 0.f;
        #pragma unroll
        for (int bb = a; bb < 8; bb++) {
            int t = tsym(8*h + a, 8*h + bb);
            float4 m0 = Mt[4*t+0], m1 = Mt[4*t+1], m2 = Mt[4*t+2], m3 = Mt[4*t+3];
            float gj0 = g[4*bb+0], gj1 = g[4*bb+1], gj2 = g[4*bb+2], gj3 = g[4*bb+3];
            y0 = fmaf(m0.x, gj0, y0); y0 = fmaf(m0.y, gj1, y0);
            y0 = fmaf(m0.z, gj2, y0); y0 = fmaf(m0.w, gj3, y0);
            y1 = fmaf(m1.x, gj0, y1); y1 = fmaf(m1.y, gj1, y1);
            y1 = fmaf(m1.z, gj2, y1); y1 = fmaf(m1.w, gj3, y1);
            y2 = fmaf(m2.x, gj0, y2); y2 = fmaf(m2.y, gj1, y2);
            y2 = fmaf(m2.z, gj2, y2); y2 = fmaf(m2.w, gj3, y2);
            y3 = fmaf(m3.x, gj0, y3); y3 = fmaf(m3.y, gj1, y3);
            y3 = fmaf(m3.z, gj2, y3); y3 = fmaf(m3.w, gj3, y3);
        }
        float s = g[4*a+0]*y0 + g[4*a+1]*y1;
        s = fmaf(g[4*a+2], y2, s);
        s = fmaf(g[4*a+3], y3, s);
        dens += s;
    }

    // cross block: tiles (a, 8+bb), split by bb range
    if (h == 0) {
        #pragma unroll
        for (int bb = 0; bb < 4; bb++) {
            float4 gj = *(const float4*)&gt[p*68 + 32 + 4*bb];
            float w0 = 0.f, w1 = 0.f, w2 = 0.f, w3 = 0.f;
            #pragma unroll
            for (int a = 0; a < 8; a++) {
                int t = tsym(a, 8 + bb);
                float4 m0 = Mt[4*t+0], m1 = Mt[4*t+1], m2 = Mt[4*t+2], m3 = Mt[4*t+3];
                float gi0 = g[4*a+0], gi1 = g[4*a+1], gi2 = g[4*a+2], gi3 = g[4*a+3];
                w0 = fmaf(m0.x, gi0, w0); w1 = fmaf(m0.y, gi0, w1);
                w2 = fmaf(m0.z, gi0, w2); w3 = fmaf(m0.w, gi0, w3);
                w0 = fmaf(m1.x, gi1, w0); w1 = fmaf(m1.y, gi1, w1);
                w2 = fmaf(m1.z, gi1, w2); w3 = fmaf(m1.w, gi1, w3);
                w0 = fmaf(m2.x, gi2, w0); w1 = fmaf(m2.y, gi2, w1);
                w2 = fmaf(m2.z, gi2, w2); w3 = fmaf(m2.w, gi2, w3);
                w0 = fmaf(m3.x, gi3, w0); w1 = fmaf(m3.y, gi3, w1);
                w2 = fmaf(m3.z, gi3, w2); w3 = fmaf(m3.w, gi3, w3);
            }
            float s = w0*gj.x + w1*gj.y;
            s = fmaf(w2, gj.z, s);
            s = fmaf(w3, gj.w, s);
            dens += s;
        }
    } else {
        #pragma unroll
        for (int a = 0; a < 8; a++) {
            float v0 = 0.f, v1 = 0.f, v2 = 0.f, v3 = 0.f;
            #pragma unroll
            for (int bb = 4; bb < 8; bb++) {
                int t = tsym(a, 8 + bb);
                float4 m0 = Mt[4*t+0], m1 = Mt[4*t+1], m2 = Mt[4*t+2], m3 = Mt[4*t+3];
                float gj0 = g[4*bb+0], gj1 = g[4*bb+1], gj2 = g[4*bb+2], gj3 = g[4*bb+3];
                v0 = fmaf(m0.x, gj0, v0); v0 = fmaf(m0.y, gj1, v0);
                v0 = fmaf(m0.z, gj2, v0); v0 = fmaf(m0.w, gj3, v0);
                v1 = fmaf(m1.x, gj0, v1); v1 = fmaf(m1.y, gj1, v1);
                v1 = fmaf(m1.z, gj2, v1); v1 = fmaf(m1.w, gj3, v1);
                v2 = fmaf(m2.x, gj0, v2); v2 = fmaf(m2.y, gj1, v2);
                v2 = fmaf(m2.z, gj2, v2); v2 = fmaf(m2.w, gj3, v2);
                v3 = fmaf(m3.x, gj0, v3); v3 = fmaf(m3.y, gj1, v3);
                v3 = fmaf(m3.z, gj2, v3); v3 = fmaf(m3.w, gj3, v3);
            }
            float4 gi = *(const float4*)&gt[p*68 + 4*a];
            float s = gi.x*v0 + gi.y*v1;
            s = fmaf(gi.z, v2, s);
            s = fmaf(gi.w, v3, s);
            dens += s;
        }
    }

    if (h == 1) pd[p] = dens;
    __syncthreads();
    if (h == 0) {
        float d = dens + pd[p];
        g_dens[(long)b*NG + g0 + p] = d;
        float mx = d;
        #pragma unroll
        for (int off = 16; off; off >>= 1)
            mx = fmaxf(mx, __shfl_xor_sync(0xffffffffu, mx, off));
        if ((tid & 31) == 0) atomicMax(&g_densmax_u, __float_as_uint(mx));
    }
}

// ---------- table: phi at NT_TAB nodes over [0, densmax] ----------
__global__ void __launch_bounds__(256) tableK(const float* __restrict__ wfb,
                                              const float* __restrict__ wpw) {
    extern __shared__ float sm[];
    float* W1   = sm;
    float* W2   = W1 + ND*ND;
    float* bufA = W2 + ND*ND;
    float* bufB = bufA + GT*ND;
    float* us   = bufB + GT*BSTRIDE;
    float* ts   = us  + ND;
    float* b1s  = ts  + ND;
    float* b2s  = b1s + ND;
    float* wps  = b2s + ND;
    int tid = threadIdx.x;

    for (int i = tid; i < ND*ND; i += 256) { W1[i] = g_W1t[i]; W2[i] = g_W2t[i]; }
    if (tid < ND) {
        us[tid]  = g_u[tid];
        ts[tid]  = g_t[tid];
        b1s[tid] = wfb[ND + tid];
        b2s[tid] = wfb[2*ND + tid];
        wps[tid] = wpw[tid];
    }
    float h = __uint_as_float(g_densmax_u) / (float)(NT_TAB - 1);
    __syncthreads();

    int t0 = blockIdx.x * GT;
    for (int i = tid; i < GT*ND; i += 256) {
        int g = i >> 7, e = i & 127;
        float x = (float)(t0 + g) * h;
        bufA[i] = fmaxf(fmaf(x, us[e], ts[e]), 0.f);
    }
    __syncthreads();

    int eq = tid & 31, gq = tid >> 5;
    float acc[8][4];
    {
        float4 bb = *(const float4*)&b1s[4*eq];
        #pragma unroll
        for (int r = 0; r < 8; r++) { acc[r][0]=bb.x; acc[r][1]=bb.y; acc[r][2]=bb.z; acc[r][3]=bb.w; }
    }
    #pragma unroll 4
    for (int d4 = 0; d4 < 32; d4++) {
        float4 w[4];
        #pragma unroll
        for (int k = 0; k < 4; k++) w[k] = *(const float4*)&W1[(4*d4 + k)*ND + 4*eq];
        #pragma unroll
        for (int r = 0; r < 8; r++) {
            float4 v = *(const float4*)&bufA[(gq*8 + r)*ND + 4*d4];
            fma4(acc[r], v.x, w[0]); fma4(acc[r], v.y, w[1]);
            fma4(acc[r], v.z, w[2]); fma4(acc[r], v.w, w[3]);
        }
    }
    #pragma unroll
    for (int r = 0; r < 8; r++) {
        float4 o = make_float4(fmaxf(acc[r][0],0.f), fmaxf(acc[r][1],0.f),
                               fmaxf(acc[r][2],0.f), fmaxf(acc[r][3],0.f));
        *(float4*)&bufB[(gq*8 + r)*BSTRIDE + 4*eq] = o;
    }
    __syncthreads();

    {
        float4 bb = *(const float4*)&b2s[4*eq];
        #pragma unroll
        for (int r = 0; r < 8; r++) { acc[r][0]=bb.x; acc[r][1]=bb.y; acc[r][2]=bb.z; acc[r][3]=bb.w; }
    }
    #pragma unroll 4
    for (int d4 = 0; d4 < 32; d4++) {
        float4 w[4];
        #pragma unroll
        for (int k = 0; k < 4; k++) w[k] = *(const float4*)&W2[(4*d4 + k)*ND + 4*eq];
        #pragma unroll
        for (int r = 0; r < 8; r++) {
            float4 v = *(const float4*)&bufB[(gq*8 + r)*BSTRIDE + 4*d4];
            fma4(acc[r], v.x, w[0]); fma4(acc[r], v.y, w[1]);
            fma4(acc[r], v.z, w[2]); fma4(acc[r], v.w, w[3]);
        }
    }
    float4 wp4 = *(const float4*)&wps[4*eq];
    #pragma unroll
    for (int r = 0; r < 8; r++) {
        float v = fmaxf(acc[r][0],0.f)*wp4.x + fmaxf(acc[r][1],0.f)*wp4.y
                + fmaxf(acc[r][2],0.f)*wp4.z + fmaxf(acc[r][3],0.f)*wp4.w;
        #pragma unroll
        for (int off = 16; off; off >>= 1) v += __shfl_xor_sync(0xffffffffu, v, off);
        if (eq == 0) g_table[t0 + gq*8 + r] = v;
    }
}

// ---------- final: E[b] += sum_g lerp(table, dens) ----------
__global__ void __launch_bounds__(256) sumK(float* __restrict__ out) {
    extern __shared__ float T[];
    float* red = T + NT_TAB;
    int tid = threadIdx.x;
    for (int i = tid; i < NT_TAB/4; i += 256)
        ((float4*)T)[i] = ((const float4*)g_table)[i];
    __syncthreads();
    float invh = (float)(NT_TAB - 1) / __uint_as_float(g_densmax_u);
    int b = blockIdx.y;
    const int chunk = NG / 8;
    long base = (long)b*NG + blockIdx.x*chunk;
    float acc = 0.f;
    for (int i = tid; i < chunk; i += 256) {
        float dn = g_dens[base + i];
        float t  = dn * invh;
        int ix = min((int)t, NT_TAB - 2);
        float f = t - (float)ix;
        acc += fmaf(f, T[ix+1] - T[ix], T[ix]);
    }
    #pragma unroll
    for (int off = 16; off; off >>= 1) acc += __shfl_xor_sync(0xffffffffu, acc, off);
    if ((tid & 31) == 0) red[tid >> 5] = acc;
    __syncthreads();
    if (tid == 0) {
        float s = 0.f;
        #pragma unroll
        for (int w = 0; w < 8; w++) s += red[w];
        atomicAdd(&out[b], s);
    }
}

extern "C" void kernel_launch(void* const* d_in, const int* in_sizes, int n_in,
                              void* d_out, int out_size) {
    const float* dist  = (const float*)d_in[0];
    const int*   qn    = (const int*)  d_in[1];
    const int*   ao    = (const int*)  d_in[2];
    const float* Ne    = (const float*)d_in[3];
    const float* coef  = (const float*)d_in[4];
    const float* zeta  = (const float*)d_in[5];
    const float* wprew = (const float*)d_in[6];
    const float* wpreb = (const float*)d_in[7];
    const float* wfw   = (const float*)d_in[8];
    const float* wfb   = (const float*)d_in[9];
    const float* wpw   = (const float*)d_in[10];
    const float* wpb   = (const float*)d_in[11];
    float* out = (float*)d_out;

    const int tabSmem = (ND*ND*2 + GT*ND + GT*BSTRIDE + ND*5) * 4;
    const int sumSmem = (NT_TAB + 8) * 4;
    cudaFuncSetAttribute(gtoGK,  cudaFuncAttributeMaxDynamicSharedMemorySize, G_SMEM);
    cudaFuncSetAttribute(prepFK, cudaFuncAttributeMaxDynamicSharedMemorySize, PF_SMEM);
    cudaFuncSetAttribute(densQK, cudaFuncAttributeMaxDynamicSharedMemorySize, DQ_SMEM);
    cudaFuncSetAttribute(tableK, cudaFuncAttributeMaxDynamicSharedMemorySize, tabSmem);
    cudaFuncSetAttribute(sumK,   cudaFuncAttributeMaxDynamicSharedMemorySize, sumSmem);

    setupK<<<12, 256>>>(out, wpb, wprew, wpreb, wfw, wfb);
    gtoGK<<<dim3(111, NB), 320, G_SMEM>>>(dist, qn, ao, zeta);
    prepFK<<<NB, 256, PF_SMEM>>>(ao, coef, Ne);
    densQK<<<dim3(NG/DQP, NB), 128, DQ_SMEM>>>(dist, qn, ao, zeta);
    tableK<<<NT_TAB/GT, 256, tabSmem>>>(wfb, wpw);
    sumK<<<dim3(8, NB), 256, sumSmem>>>(out);
}

// round 15
// speedup vs baseline: 1.1562x; 1.1468x over previous
#include <cuda_runtime.h>
#include <math.h>

#define NB 8
#define NG 32768
#define NA 64
#define ND 128
#define GT 64
#define BSTRIDE 132
#define NT_TAB 4096
#define NTILE_SYM 136      // upper-triangular 4x4 tiles of 64x64
#define DQP 64             // points per densQK block

// ---- scratch (static device allocations are allowed) ----
__device__ float g_G[NB*64*64];            // gto^T gto per molecule
__device__ float g_Mpk[NB*NTILE_SYM*16];   // packed symmetric M (off-diag doubled)
__device__ float g_dens[NB*NG];
__device__ float g_table[NT_TAB];
__device__ unsigned g_densmax_u;
__device__ float g_u[ND];
__device__ float g_t[ND];
__device__ float g_W1t[ND*ND];
__device__ float g_W2t[ND*ND];

static __device__ __forceinline__ void fma4(float* acc, float v, float4 w) {
    acc[0] = fmaf(v, w.x, acc[0]);
    acc[1] = fmaf(v, w.y, acc[1]);
    acc[2] = fmaf(v, w.z, acc[2]);
    acc[3] = fmaf(v, w.w, acc[3]);
}

static __device__ __forceinline__ float gto_val(float d, int q, float z) {
    float zd = z * d;
    float p  = (q == 0) ? 1.0f : ((q == 1) ? d : d*d);
    return p * __expf(-zd*zd);
}

// packed upper-tri tile index for 4x4 tile (TI,TJ), TI<=TJ, 16x16 tile grid
static __device__ __forceinline__ int tsym(int TI, int TJ) {
    return TI*16 - (TI*(TI+1))/2 + TJ;
}

// ---------- setup ----------
__global__ void setupK(float* out, const float* __restrict__ wpb,
                       const float* __restrict__ wprew, const float* __restrict__ wpreb,
                       const float* __restrict__ wfw,   const float* __restrict__ wfb) {
    int bid = blockIdx.x, tid = threadIdx.x;
    if (bid == 0) {
        if (tid < NB) out[tid] = wpb[0];
        if (tid == 0) g_densmax_u = 0u;
    } else if (bid == 1) {
        if (tid < ND) {
            int e = tid;
            float u = 0.f, t = 0.f;
            for (int d = 0; d < ND; d++) {
                float w = wfw[e*ND + d];
                u = fmaf(w, wprew[d], u);
                t = fmaf(w, wpreb[d], t);
            }
            g_u[e] = u;
            g_t[e] = t + wfb[e];
        }
    } else if (bid <= 3) {
        float* dst = (bid == 2) ? g_W1t : g_W2t;
        const float* src = wfw + (bid - 1) * ND * ND;
        for (int i = tid; i < ND*ND; i += 256) {
            int e = i >> 7, d = i & 127;
            dst[d*ND + e] = src[i];
        }
    } else {
        int b = bid - 4;
        for (int i = tid; i < 64*64; i += 256) g_G[b*4096 + i] = 0.f;
    }
}

// ---------- pass 1: gto from dist, syrk G += gto^T gto (4x4 tiles, dual-stream staging) ----------
#define G_SMEM ((128*68 + 64 + 64) * 4)
__global__ void __launch_bounds__(160) gtoGK(const float* __restrict__ dist,
                                             const int* __restrict__ qn,
                                             const int* __restrict__ ao,
                                             const float* __restrict__ zeta) {
    extern __shared__ float sm[];
    float* tile = sm;                    // [128][68]
    float* zs   = sm + 128*68;
    int*   qs   = (int*)(zs + 64);
    int tid = threadIdx.x;
    int b   = blockIdx.y;

    if (tid < 64) {
        qs[tid] = qn[b*NA + tid];
        zs[tid] = zeta[ao[b*NA + tid]];
    }

    int ti = 0, tj = 0;
    {
        int t = tid;
        while (ti < 16 && t >= 16 - ti) { t -= 16 - ti; ti++; }
        tj = ti + t;
    }
    bool active = (tid < 136);

    float C[4][4];
    #pragma unroll
    for (int r = 0; r < 4; r++)
        #pragma unroll
        for (int c = 0; c < 4; c++) C[r][c] = 0.f;

    __syncthreads();

    for (int tl = blockIdx.x; tl < NG/128; tl += gridDim.x) {
        const float4* src = (const float4*)(dist + ((long)b*NG + (long)tl*128) * NA);
        // dual-stream staging: two independent loads in flight per iteration
        for (int i = tid; i < 1024; i += 160) {
            float4 dv0 = src[i];
            float4 dv1 = src[i + 1024];
            int p0 = i >> 4,          c0 = i & 15;
            int p1 = (i + 1024) >> 4, c1 = c0;
            float4 gv0, gv1;
            gv0.x = gto_val(dv0.x, qs[4*c0+0], zs[4*c0+0]);
            gv0.y = gto_val(dv0.y, qs[4*c0+1], zs[4*c0+1]);
            gv0.z = gto_val(dv0.z, qs[4*c0+2], zs[4*c0+2]);
            gv0.w = gto_val(dv0.w, qs[4*c0+3], zs[4*c0+3]);
            gv1.x = gto_val(dv1.x, qs[4*c1+0], zs[4*c1+0]);
            gv1.y = gto_val(dv1.y, qs[4*c1+1], zs[4*c1+1]);
            gv1.z = gto_val(dv1.z, qs[4*c1+2], zs[4*c1+2]);
            gv1.w = gto_val(dv1.w, qs[4*c1+3], zs[4*c1+3]);
            *(float4*)&tile[p0*68 + 4*c0] = gv0;
            *(float4*)&tile[p1*68 + 4*c1] = gv1;
        }
        __syncthreads();
        if (active) {
            #pragma unroll 4
            for (int k = 0; k < 128; k++) {
                float4 ai = *(const float4*)&tile[k*68 + 4*ti];
                float4 aj = *(const float4*)&tile[k*68 + 4*tj];
                fma4(C[0], ai.x, aj); fma4(C[1], ai.y, aj);
                fma4(C[2], ai.z, aj); fma4(C[3], ai.w, aj);
            }
        }
        __syncthreads();
    }

    if (active) {
        float* Gb = g_G + b*4096;
        if (ti == tj) {
            #pragma unroll
            for (int r = 0; r < 4; r++)
                #pragma unroll
                for (int c = 0; c < 4; c++)
                    atomicAdd(&Gb[(4*ti + r)*64 + 4*tj + c], C[r][c]);
        } else {
            #pragma unroll
            for (int r = 0; r < 4; r++)
                #pragma unroll
                for (int c = 0; c < 4; c++) {
                    atomicAdd(&Gb[(4*ti + r)*64 + 4*tj + c], C[r][c]);
                    atomicAdd(&Gb[(4*tj + c)*64 + 4*ti + r], C[r][c]);
                }
        }
    }
}

// ---------- fused prep: ceff -> monorm -> packed M ----------
#define PF_SMEM ((4096 + 8448 + 64 + 128 + 128 + 256) * 4 + 64*4)
__global__ void __launch_bounds__(256) prepFK(const int* __restrict__ ao,
                                              const float* __restrict__ coef,
                                              const float* __restrict__ Ne) {
    extern __shared__ float sm[];
    float* Gs    = sm;                    // 4096
    float* ceffS = Gs + 4096;             // 64*132
    float* rg    = ceffS + 8448;          // 64
    float* rc    = rg + 64;               // 128
    float* inv   = rc + 128;              // 128
    float* mpart = inv + 128;             // 256
    int*   aos   = (int*)(mpart + 256);   // 64
    int b = blockIdx.x, tid = threadIdx.x;

    for (int i = tid; i < 4096; i += 256) Gs[i] = g_G[b*4096 + i];
    if (tid < 64) aos[tid] = ao[b*NA + tid];
    __syncthreads();
    if (tid < 64) rg[tid] = 1.f / fmaxf(sqrtf(Gs[tid*64 + tid]), 1e-12f);

    for (int i = tid; i < 64*128; i += 256) {
        int a = i >> 7, d = i & 127;
        ceffS[a*132 + d] = coef[aos[a]*ND + d];
    }
    __syncthreads();

    if (tid < 128) {
        float cn = 0.f;
        #pragma unroll 8
        for (int a = 0; a < 64; a++) { float c = ceffS[a*132 + tid]; cn = fmaf(c, c, cn); }
        rc[tid] = 1.f / fmaxf(sqrtf(cn), 1e-12f);
    }
    __syncthreads();
    for (int i = tid; i < 64*128; i += 256) {
        int a = i >> 7, d = i & 127;
        ceffS[a*132 + d] *= rc[d] * rg[a];
    }
    __syncthreads();

    {
        int d = tid & 127, h = tid >> 7;
        float c[64];
        #pragma unroll
        for (int a = 0; a < 64; a++) c[a] = ceffS[a*132 + d];
        float m = 0.f;
        int i0 = 32*h;
        for (int i = i0; i < i0 + 32; i++) {
            const float4* row = (const float4*)&Gs[i*64];
            float y0 = 0.f, y1 = 0.f, y2 = 0.f, y3 = 0.f;
            #pragma unroll
            for (int k = 0; k < 4; k++) {
                float4 ga = row[k],     gb = row[k+4];
                float4 gc = row[k+8],   gd = row[k+12];
                y0 = fmaf(ga.x, c[4*k+0],  y0); y0 = fmaf(ga.y, c[4*k+1],  y0);
                y0 = fmaf(ga.z, c[4*k+2],  y0); y0 = fmaf(ga.w, c[4*k+3],  y0);
                y1 = fmaf(gb.x, c[16+4*k+0], y1); y1 = fmaf(gb.y, c[16+4*k+1], y1);
                y1 = fmaf(gb.z, c[16+4*k+2], y1); y1 = fmaf(gb.w, c[16+4*k+3], y1);
                y2 = fmaf(gc.x, c[32+4*k+0], y2); y2 = fmaf(gc.y, c[32+4*k+1], y2);
                y2 = fmaf(gc.z, c[32+4*k+2], y2); y2 = fmaf(gc.w, c[32+4*k+3], y2);
                y3 = fmaf(gd.x, c[48+4*k+0], y3); y3 = fmaf(gd.y, c[48+4*k+1], y3);
                y3 = fmaf(gd.z, c[48+4*k+2], y3); y3 = fmaf(gd.w, c[48+4*k+3], y3);
            }
            m = fmaf(y0 + y1 + y2 + y3, c[i], m);
        }
        mpart[h*128 + d] = m;
    }
    __syncthreads();
    if (tid < 128) {
        float m = mpart[tid] + mpart[128 + tid];
        float s2 = Ne[b] / (float)ND;
        inv[tid] = sqrtf(s2 / fmaxf(m, 1e-24f));
    }
    __syncthreads();
    for (int i = tid; i < 64*128; i += 256) {
        int a = i >> 7, d = i & 127;
        ceffS[a*132 + d] *= inv[d];
    }
    __syncthreads();

    if (tid < NTILE_SYM) {
        int ti = 0, tj = 0;
        {
            int t = tid;
            while (ti < 16 && t >= 16 - ti) { t -= 16 - ti; ti++; }
            tj = ti + t;
        }
        float acc[4][4];
        #pragma unroll
        for (int r = 0; r < 4; r++)
            #pragma unroll
            for (int c = 0; c < 4; c++) acc[r][c] = 0.f;
        for (int d = 0; d < 128; d++) {
            float ci[4], cj[4];
            #pragma unroll
            for (int r = 0; r < 4; r++) ci[r] = ceffS[(4*ti + r)*132 + d];
            #pragma unroll
            for (int c = 0; c < 4; c++) cj[c] = ceffS[(4*tj + c)*132 + d];
            #pragma unroll
            for (int r = 0; r < 4; r++)
                #pragma unroll
                for (int c = 0; c < 4; c++) acc[r][c] = fmaf(ci[r], cj[c], acc[r][c]);
        }
        float sc = (ti == tj) ? 1.0f : 2.0f;
        float* dst = g_Mpk + b*NTILE_SYM*16 + tid*16;
        #pragma unroll
        for (int r = 0; r < 4; r++)
            #pragma unroll
            for (int c = 0; c < 4; c++) dst[r*4 + c] = acc[r][c] * sc;
    }
}

// ---------- pass 2: dens = g^T M g, thread-pair per point (dual-stream staging) ----------
#define DQ_SMEM ((DQP*68 + NTILE_SYM*16 + 64 + DQP) * 4 + 64*4)
__global__ void __launch_bounds__(128, 8) densQK(const float* __restrict__ dist,
                                                 const int* __restrict__ qn,
                                                 const int* __restrict__ ao,
                                                 const float* __restrict__ zeta) {
    extern __shared__ float sm[];
    float* gt = sm;                        // [DQP][68]
    float* Mp = gt + DQP*68;               // 2176
    float* zs = Mp + NTILE_SYM*16;         // 64
    float* pd = zs + 64;                   // DQP partials
    int*   qs = (int*)(pd + DQP);          // 64
    int tid = threadIdx.x;
    int b   = blockIdx.y;
    int g0  = blockIdx.x * DQP;
    int p   = tid & 63;
    int h   = tid >> 6;                    // warp-uniform half id

    if (tid < 64) {
        qs[tid] = qn[b*NA + tid];
        zs[tid] = zeta[ao[b*NA + tid]];
    }
    for (int i = tid; i < NTILE_SYM*16; i += 128) Mp[i] = g_Mpk[b*NTILE_SYM*16 + i];
    __syncthreads();

    {
        const float4* src = (const float4*)(dist + ((long)b*NG + g0) * NA);
        // dual-stream staging: 4 iterations x 2 independent loads
        for (int i = tid; i < 512; i += 128) {
            float4 dv0 = src[i];
            float4 dv1 = src[i + 512];
            int p0 = i >> 4,         c0 = i & 15;
            int p1 = (i + 512) >> 4, c1 = c0;
            float4 gv0, gv1;
            gv0.x = gto_val(dv0.x, qs[4*c0+0], zs[4*c0+0]);
            gv0.y = gto_val(dv0.y, qs[4*c0+1], zs[4*c0+1]);
            gv0.z = gto_val(dv0.z, qs[4*c0+2], zs[4*c0+2]);
            gv0.w = gto_val(dv0.w, qs[4*c0+3], zs[4*c0+3]);
            gv1.x = gto_val(dv1.x, qs[4*c1+0], zs[4*c1+0]);
            gv1.y = gto_val(dv1.y, qs[4*c1+1], zs[4*c1+1]);
            gv1.z = gto_val(dv1.z, qs[4*c1+2], zs[4*c1+2]);
            gv1.w = gto_val(dv1.w, qs[4*c1+3], zs[4*c1+3]);
            *(float4*)&gt[p0*68 + 4*c0] = gv0;
            *(float4*)&gt[p1*68 + 4*c1] = gv1;
        }
    }
    __syncthreads();

    // own half into registers
    float g[32];
    {
        const float* gp = gt + p*68 + 32*h;
        #pragma unroll
        for (int k = 0; k < 8; k++) {
            float4 v = *(const float4*)(gp + 4*k);
            g[4*k+0] = v.x; g[4*k+1] = v.y; g[4*k+2] = v.z; g[4*k+3] = v.w;
        }
    }

    const float4* Mt = (const float4*)Mp;
    float dens = 0.f;

    // own-half symmetric QF: global tiles (8h+a, 8h+bb), a<=bb
    #pragma unroll
    for (int a = 0; a < 8; a++) {
        float y0 = 0.f, y1 = 0.f, y2 = 0.f, y3 = 0.f;
        #pragma unroll
        for (int bb = a; bb < 8; bb++) {
            int t = tsym(8*h + a, 8*h + bb);
            float4 m0 = Mt[4*t+0], m1 = Mt[4*t+1], m2 = Mt[4*t+2], m3 = Mt[4*t+3];
            float gj0 = g[4*bb+0], gj1 = g[4*bb+1], gj2 = g[4*bb+2], gj3 = g[4*bb+3];
            y0 = fmaf(m0.x, gj0, y0); y0 = fmaf(m0.y, gj1, y0);
            y0 = fmaf(m0.z, gj2, y0); y0 = fmaf(m0.w, gj3, y0);
            y1 = fmaf(m1.x, gj0, y1); y1 = fmaf(m1.y, gj1, y1);
            y1 = fmaf(m1.z, gj2, y1); y1 = fmaf(m1.w, gj3, y1);
            y2 = fmaf(m2.x, gj0, y2); y2 = fmaf(m2.y, gj1, y2);
            y2 = fmaf(m2.z, gj2, y2); y2 = fmaf(m2.w, gj3, y2);
            y3 = fmaf(m3.x, gj0, y3); y3 = fmaf(m3.y, gj1, y3);
            y3 = fmaf(m3.z, gj2, y3); y3 = fmaf(m3.w, gj3, y3);
        }
        float s = g[4*a+0]*y0 + g[4*a+1]*y1;
        s = fmaf(g[4*a+2], y2, s);
        s = fmaf(g[4*a+3], y3, s);
        dens += s;
    }

    // cross block: tiles (a, 8+bb), split by bb range
    if (h == 0) {
        #pragma unroll
        for (int bb = 0; bb < 4; bb++) {
            float4 gj = *(const float4*)&gt[p*68 + 32 + 4*bb];
            float w0 = 0.f, w1 = 0.f, w2 = 0.f, w3 = 0.f;
            #pragma unroll
            for (int a = 0; a < 8; a++) {
                int t = tsym(a, 8 + bb);
                float4 m0 = Mt[4*t+0], m1 = Mt[4*t+1], m2 = Mt[4*t+2], m3 = Mt[4*t+3];
                float gi0 = g[4*a+0], gi1 = g[4*a+1], gi2 = g[4*a+2], gi3 = g[4*a+3];
                w0 = fmaf(m0.x, gi0, w0); w1 = fmaf(m0.y, gi0, w1);
                w2 = fmaf(m0.z, gi0, w2); w3 = fmaf(m0.w, gi0, w3);
                w0 = fmaf(m1.x, gi1, w0); w1 = fmaf(m1.y, gi1, w1);
                w2 = fmaf(m1.z, gi1, w2); w3 = fmaf(m1.w, gi1, w3);
                w0 = fmaf(m2.x, gi2, w0); w1 = fmaf(m2.y, gi2, w1);
                w2 = fmaf(m2.z, gi2, w2); w3 = fmaf(m2.w, gi2, w3);
                w0 = fmaf(m3.x, gi3, w0); w1 = fmaf(m3.y, gi3, w1);
                w2 = fmaf(m3.z, gi3, w2); w3 = fmaf(m3.w, gi3, w3);
            }
            float s = w0*gj.x + w1*gj.y;
            s = fmaf(w2, gj.z, s);
            s = fmaf(w3, gj.w, s);
            dens += s;
        }
    } else {
        #pragma unroll
        for (int a = 0; a < 8; a++) {
            float v0 = 0.f, v1 = 0.f, v2 = 0.f, v3 = 0.f;
            #pragma unroll
            for (int bb = 4; bb < 8; bb++) {
                int t = tsym(a, 8 + bb);
                float4 m0 = Mt[4*t+0], m1 = Mt[4*t+1], m2 = Mt[4*t+2], m3 = Mt[4*t+3];
                float gj0 = g[4*bb+0], gj1 = g[4*bb+1], gj2 = g[4*bb+2], gj3 = g[4*bb+3];
                v0 = fmaf(m0.x, gj0, v0); v0 = fmaf(m0.y, gj1, v0);
                v0 = fmaf(m0.z, gj2, v0); v0 = fmaf(m0.w, gj3, v0);
                v1 = fmaf(m1.x, gj0, v1); v1 = fmaf(m1.y, gj1, v1);
                v1 = fmaf(m1.z, gj2, v1); v1 = fmaf(m1.w, gj3, v1);
                v2 = fmaf(m2.x, gj0, v2); v2 = fmaf(m2.y, gj1, v2);
                v2 = fmaf(m2.z, gj2, v2); v2 = fmaf(m2.w, gj3, v2);
                v3 = fmaf(m3.x, gj0, v3); v3 = fmaf(m3.y, gj1, v3);
                v3 = fmaf(m3.z, gj2, v3); v3 = fmaf(m3.w, gj3, v3);
            }
            float4 gi = *(const float4*)&gt[p*68 + 4*a];
            float s = gi.x*v0 + gi.y*v1;
            s = fmaf(gi.z, v2, s);
            s = fmaf(gi.w, v3, s);
            dens += s;
        }
    }

    if (h == 1) pd[p] = dens;
    __syncthreads();
    if (h == 0) {
        float d = dens + pd[p];
        g_dens[(long)b*NG + g0 + p] = d;
        float mx = d;
        #pragma unroll
        for (int off = 16; off; off >>= 1)
            mx = fmaxf(mx, __shfl_xor_sync(0xffffffffu, mx, off));
        if ((tid & 31) == 0) atomicMax(&g_densmax_u, __float_as_uint(mx));
    }
}

// ---------- table: phi at NT_TAB nodes over [0, densmax] ----------
__global__ void __launch_bounds__(256) tableK(const float* __restrict__ wfb,
                                              const float* __restrict__ wpw) {
    extern __shared__ float sm[];
    float* W1   = sm;
    float* W2   = W1 + ND*ND;
    float* bufA = W2 + ND*ND;
    float* bufB = bufA + GT*ND;
    float* us   = bufB + GT*BSTRIDE;
    float* ts   = us  + ND;
    float* b1s  = ts  + ND;
    float* b2s  = b1s + ND;
    float* wps  = b2s + ND;
    int tid = threadIdx.x;

    for (int i = tid; i < ND*ND; i += 256) { W1[i] = g_W1t[i]; W2[i] = g_W2t[i]; }
    if (tid < ND) {
        us[tid]  = g_u[tid];
        ts[tid]  = g_t[tid];
        b1s[tid] = wfb[ND + tid];
        b2s[tid] = wfb[2*ND + tid];
        wps[tid] = wpw[tid];
    }
    float h = __uint_as_float(g_densmax_u) / (float)(NT_TAB - 1);
    __syncthreads();

    int t0 = blockIdx.x * GT;
    for (int i = tid; i < GT*ND; i += 256) {
        int g = i >> 7, e = i & 127;
        float x = (float)(t0 + g) * h;
        bufA[i] = fmaxf(fmaf(x, us[e], ts[e]), 0.f);
    }
    __syncthreads();

    int eq = tid & 31, gq = tid >> 5;
    float acc[8][4];
    {
        float4 bb = *(const float4*)&b1s[4*eq];
        #pragma unroll
        for (int r = 0; r < 8; r++) { acc[r][0]=bb.x; acc[r][1]=bb.y; acc[r][2]=bb.z; acc[r][3]=bb.w; }
    }
    #pragma unroll 4
    for (int d4 = 0; d4 < 32; d4++) {
        float4 w[4];
        #pragma unroll
        for (int k = 0; k < 4; k++) w[k] = *(const float4*)&W1[(4*d4 + k)*ND + 4*eq];
        #pragma unroll
        for (int r = 0; r < 8; r++) {
            float4 v = *(const float4*)&bufA[(gq*8 + r)*ND + 4*d4];
            fma4(acc[r], v.x, w[0]); fma4(acc[r], v.y, w[1]);
            fma4(acc[r], v.z, w[2]); fma4(acc[r], v.w, w[3]);
        }
    }
    #pragma unroll
    for (int r = 0; r < 8; r++) {
        float4 o = make_float4(fmaxf(acc[r][0],0.f), fmaxf(acc[r][1],0.f),
                               fmaxf(acc[r][2],0.f), fmaxf(acc[r][3],0.f));
        *(float4*)&bufB[(gq*8 + r)*BSTRIDE + 4*eq] = o;
    }
    __syncthreads();

    {
        float4 bb = *(const float4*)&b2s[4*eq];
        #pragma unroll
        for (int r = 0; r < 8; r++) { acc[r][0]=bb.x; acc[r][1]=bb.y; acc[r][2]=bb.z; acc[r][3]=bb.w; }
    }
    #pragma unroll 4
    for (int d4 = 0; d4 < 32; d4++) {
        float4 w[4];
        #pragma unroll
        for (int k = 0; k < 4; k++) w[k] = *(const float4*)&W2[(4*d4 + k)*ND + 4*eq];
        #pragma unroll
        for (int r = 0; r < 8; r++) {
            float4 v = *(const float4*)&bufB[(gq*8 + r)*BSTRIDE + 4*d4];
            fma4(acc[r], v.x, w[0]); fma4(acc[r], v.y, w[1]);
            fma4(acc[r], v.z, w[2]); fma4(acc[r], v.w, w[3]);
        }
    }
    float4 wp4 = *(const float4*)&wps[4*eq];
    #pragma unroll
    for (int r = 0; r < 8; r++) {
        float v = fmaxf(acc[r][0],0.f)*wp4.x + fmaxf(acc[r][1],0.f)*wp4.y
                + fmaxf(acc[r][2],0.f)*wp4.z + fmaxf(acc[r][3],0.f)*wp4.w;
        #pragma unroll
        for (int off = 16; off; off >>= 1) v += __shfl_xor_sync(0xffffffffu, v, off);
        if (eq == 0) g_table[t0 + gq*8 + r] = v;
    }
}

// ---------- final: E[b] += sum_g lerp(table, dens) ----------
__global__ void __launch_bounds__(256) sumK(float* __restrict__ out) {
    extern __shared__ float T[];
    float* red = T + NT_TAB;
    int tid = threadIdx.x;
    for (int i = tid; i < NT_TAB/4; i += 256)
        ((float4*)T)[i] = ((const float4*)g_table)[i];
    __syncthreads();
    float invh = (float)(NT_TAB - 1) / __uint_as_float(g_densmax_u);
    int b = blockIdx.y;
    const int chunk = NG / 8;
    long base = (long)b*NG + blockIdx.x*chunk;
    float acc = 0.f;
    for (int i = tid; i < chunk; i += 256) {
        float dn = g_dens[base + i];
        float t  = dn * invh;
        int ix = min((int)t, NT_TAB - 2);
        float f = t - (float)ix;
        acc += fmaf(f, T[ix+1] - T[ix], T[ix]);
    }
    #pragma unroll
    for (int off = 16; off; off >>= 1) acc += __shfl_xor_sync(0xffffffffu, acc, off);
    if ((tid & 31) == 0) red[tid >> 5] = acc;
    __syncthreads();
    if (tid == 0) {
        float s = 0.f;
        #pragma unroll
        for (int w = 0; w < 8; w++) s += red[w];
        atomicAdd(&out[b], s);
    }
}

extern "C" void kernel_launch(void* const* d_in, const int* in_sizes, int n_in,
                              void* d_out, int out_size) {
    const float* dist  = (const float*)d_in[0];
    const int*   qn    = (const int*)  d_in[1];
    const int*   ao    = (const int*)  d_in[2];
    const float* Ne    = (const float*)d_in[3];
    const float* coef  = (const float*)d_in[4];
    const float* zeta  = (const float*)d_in[5];
    const float* wprew = (const float*)d_in[6];
    const float* wpreb = (const float*)d_in[7];
    const float* wfw   = (const float*)d_in[8];
    const float* wfb   = (const float*)d_in[9];
    const float* wpw   = (const float*)d_in[10];
    const float* wpb   = (const float*)d_in[11];
    float* out = (float*)d_out;

    const int tabSmem = (ND*ND*2 + GT*ND + GT*BSTRIDE + ND*5) * 4;
    const int sumSmem = (NT_TAB + 8) * 4;
    cudaFuncSetAttribute(gtoGK,  cudaFuncAttributeMaxDynamicSharedMemorySize, G_SMEM);
    cudaFuncSetAttribute(prepFK, cudaFuncAttributeMaxDynamicSharedMemorySize, PF_SMEM);
    cudaFuncSetAttribute(densQK, cudaFuncAttributeMaxDynamicSharedMemorySize, DQ_SMEM);
    cudaFuncSetAttribute(tableK, cudaFuncAttributeMaxDynamicSharedMemorySize, tabSmem);
    cudaFuncSetAttribute(sumK,   cudaFuncAttributeMaxDynamicSharedMemorySize, sumSmem);

    setupK<<<12, 256>>>(out, wpb, wprew, wpreb, wfw, wfb);
    gtoGK<<<dim3(111, NB), 160, G_SMEM>>>(dist, qn, ao, zeta);
    prepFK<<<NB, 256, PF_SMEM>>>(ao, coef, Ne);
    densQK<<<dim3(NG/DQP, NB), 128, DQ_SMEM>>>(dist, qn, ao, zeta);
    tableK<<<NT_TAB/GT, 256, tabSmem>>>(wfb, wpw);
    sumK<<<dim3(8, NB), 256, sumSmem>>>(out);
}